// round 11
// baseline (speedup 1.0000x reference)
#include <cuda_runtime.h>
#include <cuda_fp16.h>
#include <cstdint>

// Problem constants
#define B_   8
#define N_   2048
#define F0_  128
#define HID_ 64
#define OUT_ 16
#define K_   10

#define VCHUNKS 32                  // 64 rows per chunk
#define RPC     64                  // rows per chunk
#define GRID    256                 // 8 wtiles x 32 vchunks
#define TPB     128
#define NGROUP  8                   // barrier tree fan-in groups

// ---------------- device scratch (static; no allocation) ----------------
__device__ float g_zvec[2][N_];              // persisted z_{j-1} ping-pong
__device__ float g_pz[2][VCHUNKS][N_];       // double-buffered partials of L^T z
__device__ float g_pr[2][VCHUNKS][N_];       // double-buffered partials of L^T r
__device__ float g_part[B_][32][HID_];       // per-(b,chunk) partial Hg sums
__device__ unsigned g_grp[NGROUP * 32];      // group counters, 128B apart
__device__ unsigned g_root = 0;              // root counter
__device__ unsigned g_release = 0;           // release generation (monotonic)

__constant__ float c_binom[K_ + 1] = {1.f, 10.f, 45.f, 120.f, 210.f, 252.f,
                                      210.f, 120.f, 45.f, 10.f, 1.f};

// ---- tree grid barrier: 8-way distributed arrivals, acq/rel semantics ----
__device__ __forceinline__ void gsync(int tid, int bid, unsigned gen) {
    __syncthreads();
    if (tid == 0) {
        unsigned t;
        asm volatile("atom.add.acq_rel.gpu.global.u32 %0, [%1], 1;"
                     : "=r"(t) : "l"(&g_grp[(bid & (NGROUP - 1)) * 32]) : "memory");
        if (t + 1u == (GRID / NGROUP) * gen) {        // my group complete
            unsigned rt;
            asm volatile("atom.add.acq_rel.gpu.global.u32 %0, [%1], 1;"
                         : "=r"(rt) : "l"(&g_root) : "memory");
            if (rt + 1u == NGROUP * gen) {            // all groups complete
                asm volatile("red.add.release.gpu.global.u32 [%0], 1;"
                             :: "l"(&g_release) : "memory");
            }
        }
        unsigned r;
        do {
            asm volatile("ld.acquire.gpu.global.u32 %0, [%1];"
                         : "=r"(r) : "l"(&g_release) : "memory");
        } while (r < gen);
    }
    __syncthreads();
}

__global__ __launch_bounds__(TPB) void mega_kernel(
    const float* __restrict__ X,  const float* __restrict__ L,
    const float* __restrict__ W1, const float* __restrict__ b1,
    const float* __restrict__ W2, const float* __restrict__ b2,
    const float* __restrict__ theta, float* __restrict__ out)
{
    extern __shared__ char dynsmem[];            // 32 KB: L-tile, later W1
    __half2* tile = reinterpret_cast<__half2*>(dynsmem);   // [64][128]
    float*   w1s  = reinterpret_cast<float*>(dynsmem);     // hf-phase alias

    __shared__ float sz[RPC], sr[RPC];
    __shared__ float b1s[HID_];
    __shared__ float vsh[RPC];
    __shared__ float red[4][32];
    __shared__ float hg[B_ * HID_];

    const int tid = threadIdx.x;
    const int bid = blockIdx.x;
    const int wtile = bid & 7;
    const int vchunk = bid >> 3;
    const int v0 = vchunk * RPC;

    // generation base: stable until every block has arrived once (each block
    // seeds before its first arrival), so all blocks read the same value.
    unsigned gen = 0;
    if (tid == 0) {
        asm volatile("ld.relaxed.gpu.global.u32 %0, [%1];"
                     : "=r"(gen) : "l"(&g_release));
    }

    // ---- Phase 0: convert MY 64x256 fp32 L tile into smem fp16 ----------
    {
        const float* Lsrc = L + (size_t)v0 * N_ + wtile * 256;
        for (int i = tid; i < 64 * 64; i += TPB) {     // 64 rows x 64 float4
            int row = i >> 6, q = i & 63;
            float4 f = reinterpret_cast<const float4*>(Lsrc + (size_t)row * N_)[q];
            tile[row * 128 + 2 * q]     = __floats2half2_rn(f.x, f.y);
            tile[row * 128 + 2 * q + 1] = __floats2half2_rn(f.z, f.w);
        }
    }
    __syncthreads();

    // ---- Passes 1..K: recon z/r for my chunk, partial dots from smem ----
    const int half = tid >> 6;          // 0: z-recon, 1: r-recon
    const int t = tid & 63;
    const int v = v0 + t;

    for (int j = 1; j <= K_; ++j) {
        const int pout = j & 1;
        const int pin  = pout ^ 1;

        if (j > 1) gsync(tid, bid, ++gen);   // partials of pass j-1 complete

        if (j == 1) {
            if (half == 0) sz[t] = 1.0f;                       // z_0
            else           sr[t] = theta[K_];                  // r_0 = a_K
        } else if (half == 0) {
            float s = 0.f;
#pragma unroll
            for (int c = 0; c < VCHUNKS; ++c) s += g_pz[pin][c][v];
            float zold = (j == 2) ? 1.0f : g_zvec[pin][v];
            float znew = zold - s;
            sz[t] = znew;
            if (wtile == 0) g_zvec[pout][v] = znew;            // persist z_{j-1}
        } else {
            float s = 0.f, sp = 0.f;
#pragma unroll
            for (int c = 0; c < VCHUNKS; ++c) {
                s  += g_pz[pin][c][v];
                sp += g_pr[pin][c][v];
            }
            float zold = (j == 2) ? 1.0f : g_zvec[pin][v];
            float znew = zold - s;
            float aj = theta[K_ - j + 1] * c_binom[K_ - j + 1];
            sr[t] = sp + aj * znew;
        }
        __syncthreads();

        float az0 = 0.f, az1 = 0.f, ar0 = 0.f, ar1 = 0.f;
#pragma unroll
        for (int vv = 0; vv < RPC; ++vv) {
            float2 f = __half22float2(tile[vv * 128 + tid]);
            float zc = sz[vv], rc = sr[vv];
            az0 += f.x * zc;  az1 += f.y * zc;
            ar0 += f.x * rc;  ar1 += f.y * rc;
        }
        const int w2 = wtile * 128 + tid;
        reinterpret_cast<float2*>(g_pz[pout][vchunk])[w2] = make_float2(az0, az1);
        reinterpret_cast<float2*>(g_pr[pout][vchunk])[w2] = make_float2(ar0, ar1);
        __syncthreads();
    }

    gsync(tid, bid, ++gen);              // pass-K partials complete (parity 0)

    // ---- hf phase: remap blocks, reconstruct v, GEMM + weighted reduce --
    {
        const int chunk = bid & 31;
        const int b = bid >> 5;
        const int tx = tid & 63;
        const int ty = tid >> 6;

        if (ty == 0) {                   // v[n] for my 64-row chunk
            int n = chunk * 64 + tx;
            float s = 0.f, sp = 0.f;
#pragma unroll
            for (int c = 0; c < VCHUNKS; ++c) {
                s  += g_pz[0][c][n];
                sp += g_pr[0][c][n];
            }
            float znew = g_zvec[0][n] - s;
            vsh[tx] = sp + theta[0] * znew;       // a_0 = theta_0 * 1
        }
        __syncthreads();                 // tile dead -> safe to overwrite

        for (int i = tid; i < F0_ * HID_; i += TPB) w1s[i] = W1[i];
        if (tid < HID_) b1s[tid] = b1[tid];
        __syncthreads();

        const int n = chunk * 64 + tx;
        const float* xr = X + ((size_t)b * N_ + n) * F0_;
        const int h0 = ty * 32;

        float acc[32];
#pragma unroll
        for (int h = 0; h < 32; ++h) acc[h] = b1s[h0 + h];

        for (int f0 = 0; f0 < F0_; f0 += 16) {
            float4 xv[4];
#pragma unroll
            for (int i = 0; i < 4; ++i)
                xv[i] = reinterpret_cast<const float4*>(xr + f0)[i];
            const float* xf = reinterpret_cast<const float*>(xv);
#pragma unroll
            for (int i = 0; i < 16; ++i) {
                float x = xf[i];
                const float4* wrow =
                    reinterpret_cast<const float4*>(&w1s[(f0 + i) * HID_ + h0]);
#pragma unroll
                for (int q = 0; q < 8; ++q) {
                    float4 wv = wrow[q];
                    acc[q * 4 + 0] += x * wv.x;
                    acc[q * 4 + 1] += x * wv.y;
                    acc[q * 4 + 2] += x * wv.z;
                    acc[q * 4 + 3] += x * wv.w;
                }
            }
        }

        float s = vsh[tx] * (1.0f / (float)N_);
#pragma unroll
        for (int h = 0; h < 32; ++h) acc[h] = fmaxf(acc[h], 0.f) * s;

#pragma unroll
        for (int h = 0; h < 32; ++h) {
            float v_ = acc[h];
            v_ += __shfl_xor_sync(0xffffffffu, v_, 16);
            v_ += __shfl_xor_sync(0xffffffffu, v_, 8);
            v_ += __shfl_xor_sync(0xffffffffu, v_, 4);
            v_ += __shfl_xor_sync(0xffffffffu, v_, 2);
            v_ += __shfl_xor_sync(0xffffffffu, v_, 1);
            acc[h] = v_;
        }
        int lane = tid & 31, warp = tid >> 5;
        if (lane == 0) {
#pragma unroll
            for (int h = 0; h < 32; ++h) red[warp][h] = acc[h];
        }
        __syncthreads();
        if (tid < 64) {
            int hh = tid & 31;
            int grp = tid >> 5;
            g_part[b][chunk][grp * 32 + hh] = red[grp * 2][hh] + red[grp * 2 + 1][hh];
        }
    }

    gsync(tid, bid, ++gen);              // all g_part written

    // ---- final: block 0 reduces chunks, logits = Hg@W2 + b2 ------------
    if (bid == 0) {
        for (int i = tid; i < B_ * HID_; i += TPB) {
            int bb = i >> 6, hh = i & 63;
            float s = 0.f;
#pragma unroll
            for (int c = 0; c < 32; ++c) s += g_part[bb][c][hh];
            hg[i] = s;
        }
        __syncthreads();
        {   // 128 threads = 8 batches x 16 outputs
            int bb = tid >> 4, o = tid & 15;
            float acc = b2[o];
#pragma unroll
            for (int hh = 0; hh < HID_; ++hh)
                acc += hg[bb * HID_ + hh] * W2[hh * OUT_ + o];
            out[bb * OUT_ + o] = acc;
        }
    }
}

// ---------------- launcher ----------------------------------------------
extern "C" void kernel_launch(void* const* d_in, const int* in_sizes, int n_in,
                              void* d_out, int out_size) {
    const float* X     = (const float*)d_in[0];
    const float* L     = (const float*)d_in[1];
    const float* W1    = (const float*)d_in[2];
    const float* b1    = (const float*)d_in[3];
    const float* W2    = (const float*)d_in[4];
    const float* b2    = (const float*)d_in[5];
    const float* theta = (const float*)d_in[6];
    float* out = (float*)d_out;

    mega_kernel<<<GRID, TPB, 32 * 1024>>>(X, L, W1, b1, W2, b2, theta, out);
}

// round 12
// speedup vs baseline: 1.9839x; 1.9839x over previous
#include <cuda_runtime.h>
#include <cuda_fp16.h>
#include <cstdint>

// Problem constants
#define B_   8
#define N_   2048
#define F0_  128
#define HID_ 64
#define OUT_ 16
#define K_   10

#define VCHUNKS 32                  // 64 rows per chunk
#define RPC     64                  // rows per chunk
#define GRIDF   256                 // filter blocks (barrier population)
#define GRIDH   256                 // hf blocks
#define TPB     128

// ---------------- device scratch (static; no allocation) ----------------
__device__ float g_zvec[2][N_];              // persisted z_{j-1} ping-pong
__device__ float g_pz[2][VCHUNKS][N_];       // double-buffered partials of L^T z
__device__ float g_pr[2][VCHUNKS][N_];       // double-buffered partials of L^T r
__device__ float g_part[B_][32][HID_];       // per-(b,chunk) partial Hg sums
__device__ unsigned g_barcnt = 0;            // monotonic ticket counter
__device__ unsigned g_barrel = 0;            // monotonic release generation
__device__ unsigned g_hfdone = 0;            // monotonic hf completion counter

__constant__ float c_binom[K_ + 1] = {1.f, 10.f, 45.f, 120.f, 210.f, 252.f,
                                      210.f, 120.f, 45.f, 10.f, 1.f};

// ---- proven round-9 grid barrier (filter blocks only) --------------------
__device__ __forceinline__ void grid_arrive_wait() {
    __threadfence();
    unsigned ticket = atomicAdd(&g_barcnt, 1u) + 1u;
    unsigned gen = (ticket + GRIDF - 1u) / GRIDF;
    if ((ticket & (GRIDF - 1u)) == 0u) {
        atomicAdd(&g_barrel, 1u);
    }
    int spins = 0;
    while (*((volatile unsigned*)&g_barrel) < gen) {
        if (++spins > 64) __nanosleep(32);
    }
    __threadfence();
}

__device__ __forceinline__ void gsync(int tid) {
    __syncthreads();
    if (tid == 0) grid_arrive_wait();
    __syncthreads();
}

__global__ __launch_bounds__(TPB) void mega_kernel(
    const float* __restrict__ X,  const float* __restrict__ L,
    const float* __restrict__ W1, const float* __restrict__ b1,
    const float* __restrict__ W2, const float* __restrict__ b2,
    const float* __restrict__ theta, float* __restrict__ out)
{
    extern __shared__ char dynsmem[];            // 32 KB: L-tile or W1
    __half2* tile = reinterpret_cast<__half2*>(dynsmem);   // filter: [64][128]
    float*   w1s  = reinterpret_cast<float*>(dynsmem);     // hf: W1

    __shared__ float sz[RPC], sr[RPC];
    __shared__ float b1s[HID_];
    __shared__ float vsh[RPC];
    __shared__ float red[4][32];
    __shared__ float hg[B_ * HID_];
    __shared__ unsigned sbase;

    const int tid = threadIdx.x;
    const int bid = blockIdx.x;

    if (bid < GRIDF) {
        // =================== FILTER BLOCKS (round-9 verbatim) =============
        const int wtile = bid & 7;
        const int vchunk = bid >> 3;
        const int v0 = vchunk * RPC;

        // block 0 snapshots hf-done base at entry (monotonic counter).
        // Safe: hf arrivals require release+10, which needs block 0's own
        // 10 barrier arrivals -> no hf arrival can precede this read.
        if (bid == 0 && tid == 0) sbase = *((volatile unsigned*)&g_hfdone);

        // ---- Phase 0: convert MY 64x256 fp32 L tile into smem fp16 ------
        {
            const float* Lsrc = L + (size_t)v0 * N_ + wtile * 256;
            for (int i = tid; i < 64 * 64; i += TPB) {   // 64 rows x 64 float4
                int row = i >> 6, q = i & 63;
                float4 f = reinterpret_cast<const float4*>(Lsrc + (size_t)row * N_)[q];
                tile[row * 128 + 2 * q]     = __floats2half2_rn(f.x, f.y);
                tile[row * 128 + 2 * q + 1] = __floats2half2_rn(f.z, f.w);
            }
        }
        __syncthreads();

        // ---- Passes 1..K: recon z/r for my chunk, dots from smem --------
        const int half = tid >> 6;      // 0: z-recon, 1: r-recon
        const int t = tid & 63;
        const int v = v0 + t;

        for (int j = 1; j <= K_; ++j) {
            const int pout = j & 1;
            const int pin  = pout ^ 1;

            if (j > 1) gsync(tid);      // partials of pass j-1 complete

            if (j == 1) {
                if (half == 0) sz[t] = 1.0f;                   // z_0
                else           sr[t] = theta[K_];              // r_0 = a_K
            } else if (half == 0) {
                float s = 0.f;
#pragma unroll
                for (int c = 0; c < VCHUNKS; ++c) s += g_pz[pin][c][v];
                float zold = (j == 2) ? 1.0f : g_zvec[pin][v];
                float znew = zold - s;
                sz[t] = znew;
                if (wtile == 0) g_zvec[pout][v] = znew;        // persist z_{j-1}
            } else {
                float s = 0.f, sp = 0.f;
#pragma unroll
                for (int c = 0; c < VCHUNKS; ++c) {
                    s  += g_pz[pin][c][v];
                    sp += g_pr[pin][c][v];
                }
                float zold = (j == 2) ? 1.0f : g_zvec[pin][v];
                float znew = zold - s;
                float aj = theta[K_ - j + 1] * c_binom[K_ - j + 1];
                sr[t] = sp + aj * znew;
            }
            __syncthreads();

            float az0 = 0.f, az1 = 0.f, ar0 = 0.f, ar1 = 0.f;
#pragma unroll
            for (int vv = 0; vv < RPC; ++vv) {
                float2 f = __half22float2(tile[vv * 128 + tid]);
                float zc = sz[vv], rc = sr[vv];
                az0 += f.x * zc;  az1 += f.y * zc;
                ar0 += f.x * rc;  ar1 += f.y * rc;
            }
            const int w2 = wtile * 128 + tid;
            reinterpret_cast<float2*>(g_pz[pout][vchunk])[w2] = make_float2(az0, az1);
            reinterpret_cast<float2*>(g_pr[pout][vchunk])[w2] = make_float2(ar0, ar1);
            __syncthreads();
        }

        // ---- final arrival (10th round): releases hf blocks. No wait. ---
        __syncthreads();
        if (tid == 0) {
            __threadfence();
            unsigned ticket = atomicAdd(&g_barcnt, 1u) + 1u;
            if ((ticket & (GRIDF - 1u)) == 0u) atomicAdd(&g_barrel, 1u);
        }

        // ---- block 0: wait for all hf partials, emit logits -------------
        if (bid == 0) {
            if (tid == 0) {
                unsigned target = sbase + GRIDH;
                int spins = 0;
                while (*((volatile unsigned*)&g_hfdone) < target) {
                    if (++spins > 16) __nanosleep(64);
                }
                __threadfence();
            }
            __syncthreads();

            for (int i = tid; i < B_ * HID_; i += TPB) {
                int bb = i >> 6, hh = i & 63;
                float s = 0.f;
#pragma unroll
                for (int c = 0; c < 32; ++c) s += g_part[bb][c][hh];
                hg[i] = s;
            }
            __syncthreads();
            {   // 128 threads = 8 batches x 16 outputs
                int bb = tid >> 4, o = tid & 15;
                float acc = b2[o];
#pragma unroll
                for (int hh = 0; hh < HID_; ++hh)
                    acc += hg[bb * HID_ + hh] * W2[hh * OUT_ + o];
                out[bb * OUT_ + o] = acc;
            }
        }
    } else {
        // =================== HF BLOCKS (overlap with filter) ==============
        const int hbid = bid - GRIDF;
        const int chunk = hbid & 31;
        const int b = hbid >> 5;
        const int tx = tid & 63;
        const int ty = tid >> 6;

        // snapshot release base at entry (before any filter barrier can
        // complete: first barrier needs all 256 filter blocks through the
        // ~5us convert phase; we read within ~100ns of block start).
        if (tid == 0) sbase = *((volatile unsigned*)&g_barrel);
        __syncthreads();
        const unsigned rbase = sbase;

        // ---- hf GEMM: acc = relu-pending (X@W1 + b1), overlapped --------
        for (int i = tid; i < F0_ * HID_; i += TPB) w1s[i] = W1[i];
        if (tid < HID_) b1s[tid] = b1[tid];
        __syncthreads();

        const int n = chunk * 64 + tx;
        const float* xr = X + ((size_t)b * N_ + n) * F0_;
        const int h0 = ty * 32;

        float acc[32];
#pragma unroll
        for (int h = 0; h < 32; ++h) acc[h] = b1s[h0 + h];

        for (int f0 = 0; f0 < F0_; f0 += 16) {
            float4 xv[4];
#pragma unroll
            for (int i = 0; i < 4; ++i)
                xv[i] = reinterpret_cast<const float4*>(xr + f0)[i];
            const float* xf = reinterpret_cast<const float*>(xv);
#pragma unroll
            for (int i = 0; i < 16; ++i) {
                float x = xf[i];
                const float4* wrow =
                    reinterpret_cast<const float4*>(&w1s[(f0 + i) * HID_ + h0]);
#pragma unroll
                for (int q = 0; q < 8; ++q) {
                    float4 wv = wrow[q];
                    acc[q * 4 + 0] += x * wv.x;
                    acc[q * 4 + 1] += x * wv.y;
                    acc[q * 4 + 2] += x * wv.z;
                    acc[q * 4 + 3] += x * wv.w;
                }
            }
        }

        // ---- wait for filter chain completion (release + 10 rounds) -----
        if (tid == 0) {
            unsigned target = rbase + K_;        // 10 barrier rounds
            int spins = 0;
            while (*((volatile unsigned*)&g_barrel) < target) {
                if (++spins > 4) __nanosleep(128);
            }
            __threadfence();
        }
        __syncthreads();

        // ---- reconstruct v for my 64-row chunk --------------------------
        if (ty == 0) {
            int nn = chunk * 64 + tx;
            float s = 0.f, sp = 0.f;
#pragma unroll
            for (int c = 0; c < VCHUNKS; ++c) {
                s  += g_pz[0][c][nn];
                sp += g_pr[0][c][nn];
            }
            float znew = g_zvec[0][nn] - s;
            vsh[tx] = sp + theta[0] * znew;       // a_0 = theta_0
        }
        __syncthreads();

        float s = vsh[tx] * (1.0f / (float)N_);
#pragma unroll
        for (int h = 0; h < 32; ++h) acc[h] = fmaxf(acc[h], 0.f) * s;

#pragma unroll
        for (int h = 0; h < 32; ++h) {
            float v_ = acc[h];
            v_ += __shfl_xor_sync(0xffffffffu, v_, 16);
            v_ += __shfl_xor_sync(0xffffffffu, v_, 8);
            v_ += __shfl_xor_sync(0xffffffffu, v_, 4);
            v_ += __shfl_xor_sync(0xffffffffu, v_, 2);
            v_ += __shfl_xor_sync(0xffffffffu, v_, 1);
            acc[h] = v_;
        }
        int lane = tid & 31, warp = tid >> 5;
        if (lane == 0) {
#pragma unroll
            for (int h = 0; h < 32; ++h) red[warp][h] = acc[h];
        }
        __syncthreads();
        if (tid < 64) {
            int hh = tid & 31;
            int grp = tid >> 5;
            g_part[b][chunk][grp * 32 + hh] = red[grp * 2][hh] + red[grp * 2 + 1][hh];
        }

        // ---- signal completion ------------------------------------------
        __syncthreads();
        if (tid == 0) {
            __threadfence();
            atomicAdd(&g_hfdone, 1u);
        }
    }
}

// ---------------- launcher ----------------------------------------------
extern "C" void kernel_launch(void* const* d_in, const int* in_sizes, int n_in,
                              void* d_out, int out_size) {
    const float* X     = (const float*)d_in[0];
    const float* L     = (const float*)d_in[1];
    const float* W1    = (const float*)d_in[2];
    const float* b1    = (const float*)d_in[3];
    const float* W2    = (const float*)d_in[4];
    const float* b2    = (const float*)d_in[5];
    const float* theta = (const float*)d_in[6];
    float* out = (float*)d_out;

    mega_kernel<<<GRIDF + GRIDH, TPB, 32 * 1024>>>(X, L, W1, b1, W2, b2, theta, out);
}

// round 13
// speedup vs baseline: 2.1449x; 1.0811x over previous
#include <cuda_runtime.h>
#include <cuda_fp16.h>
#include <cstdint>

// Problem constants
#define B_   8
#define N_   2048
#define F0_  128
#define HID_ 64
#define OUT_ 16
#define K_   10

#define VCHUNKS 32                  // 64 rows per chunk
#define RPC     64                  // rows per chunk
#define GRIDF   256                 // filter blocks: 8 wtiles x 32 vchunks
#define GRIDH   256                 // hf blocks
#define TPB     128

// ---------------- device scratch (static; no allocation) ----------------
__device__ float g_zv[K_ + 1][N_];               // z_j vectors (z_0 implicit = 1)
__device__ float g_pz[K_ + 1][VCHUNKS][N_];      // per-pass partials of L^T z
__device__ float g_pr[K_ + 1][VCHUNKS][N_];      // per-pass partials of L^T r
__device__ float g_part[B_][32][HID_];           // per-(b,chunk) weighted partials
__device__ unsigned g_cnt[8 * 32];               // per-wtile-group counters, 128B apart
__device__ unsigned g_hfdone = 0;                // monotonic hf completion counter

__constant__ float c_binom[K_ + 1] = {1.f, 10.f, 45.f, 120.f, 210.f, 252.f,
                                      210.f, 120.f, 45.f, 10.f, 1.f};

// ---- consumer-side wait on a group counter (tid-0 poll, proven pattern) --
__device__ __forceinline__ void wait_cnt(volatile unsigned* ctr, unsigned target) {
    int spins = 0;
    while (*ctr < target) {
        if (++spins > 64) __nanosleep(32);
    }
    __threadfence();
}

__global__ __launch_bounds__(TPB) void mega_kernel(
    const float* __restrict__ X,  const float* __restrict__ L,
    const float* __restrict__ W1, const float* __restrict__ b1,
    const float* __restrict__ W2, const float* __restrict__ b2,
    const float* __restrict__ theta, float* __restrict__ out)
{
    extern __shared__ char dynsmem[];            // 32 KB: L-tile or W1
    __half2* tile = reinterpret_cast<__half2*>(dynsmem);   // filter: [64][128]
    float*   w1s  = reinterpret_cast<float*>(dynsmem);     // hf: W1

    __shared__ float sz[RPC], sr[RPC];
    __shared__ float b1s[HID_];
    __shared__ float vsh[RPC];
    __shared__ float red[4][32];
    __shared__ float hg[B_ * HID_];
    __shared__ unsigned sbase;       // input-group counter base
    __shared__ unsigned shbase;      // hf-done base (block 0)

    const int tid = threadIdx.x;
    const int bid = blockIdx.x;

    if (bid < GRIDF) {
        // =================== FILTER BLOCKS ================================
        const int wtile = bid & 7;
        const int vchunk = bid >> 3;
        const int v0 = vchunk * RPC;
        const int gin = vchunk >> 2;              // producer group I consume
        const bool zwriter = (wtile == gin);      // designated z_vec writer

        // snapshot bases at entry (monotonic counters; safe: first arrival
        // of this replay requires a ~2us convert, snapshots in ~100ns)
        if (tid == 0) {
            sbase = *((volatile unsigned*)&g_cnt[gin * 32]);
            if (bid == 0) shbase = *((volatile unsigned*)&g_hfdone);
        }

        // ---- Phase 0: convert MY 64x256 fp32 L tile into smem fp16 ------
        {
            const float* Lsrc = L + (size_t)v0 * N_ + wtile * 256;
            for (int i = tid; i < 64 * 64; i += TPB) {   // 64 rows x 64 float4
                int row = i >> 6, q = i & 63;
                float4 f = reinterpret_cast<const float4*>(Lsrc + (size_t)row * N_)[q];
                tile[row * 128 + 2 * q]     = __floats2half2_rn(f.x, f.y);
                tile[row * 128 + 2 * q + 1] = __floats2half2_rn(f.z, f.w);
            }
        }
        __syncthreads();
        const unsigned cbase = sbase;

        // ---- Passes 1..K: dataflow-synced recon + dots ------------------
        const int half = tid >> 6;      // 0: z-recon, 1: r-recon
        const int t = tid & 63;
        const int v = v0 + t;

        for (int j = 1; j <= K_; ++j) {
            if (j > 1) {                 // wait: my input group wrote pass j-1
                if (tid == 0)
                    wait_cnt((volatile unsigned*)&g_cnt[gin * 32],
                             cbase + 32u * (unsigned)(j - 1));
                __syncthreads();
            }

            if (j == 1) {
                if (half == 0) sz[t] = 1.0f;                   // z_0
                else           sr[t] = theta[K_];              // r_0 = a_K
            } else if (half == 0) {
                float s = 0.f;
#pragma unroll
                for (int c = 0; c < VCHUNKS; ++c) s += g_pz[j - 1][c][v];
                float zold = (j == 2) ? 1.0f : g_zv[j - 2][v];
                float znew = zold - s;
                sz[t] = znew;
                if (zwriter) g_zv[j - 1][v] = znew;            // persist z_{j-1}
            } else {
                float s = 0.f, sp = 0.f;
#pragma unroll
                for (int c = 0; c < VCHUNKS; ++c) {
                    s  += g_pz[j - 1][c][v];
                    sp += g_pr[j - 1][c][v];
                }
                float zold = (j == 2) ? 1.0f : g_zv[j - 2][v];
                float znew = zold - s;
                float aj = theta[K_ - j + 1] * c_binom[K_ - j + 1];
                sr[t] = sp + aj * znew;
            }
            __syncthreads();

            float az0 = 0.f, az1 = 0.f, ar0 = 0.f, ar1 = 0.f;
#pragma unroll
            for (int vv = 0; vv < RPC; ++vv) {
                float2 f = __half22float2(tile[vv * 128 + tid]);
                float zc = sz[vv], rc = sr[vv];
                az0 += f.x * zc;  az1 += f.y * zc;
                ar0 += f.x * rc;  ar1 += f.y * rc;
            }
            const int w2 = wtile * 128 + tid;
            reinterpret_cast<float2*>(g_pz[j][vchunk])[w2] = make_float2(az0, az1);
            reinterpret_cast<float2*>(g_pr[j][vchunk])[w2] = make_float2(ar0, ar1);
            __syncthreads();

            if (tid == 0) {              // arrive on MY group's counter
                __threadfence();
                atomicAdd(&g_cnt[wtile * 32], 1u);
            }
        }

        // ---- block 0: wait for all hf partials, emit logits -------------
        if (bid == 0) {
            if (tid == 0) {
                unsigned target = shbase + GRIDH;
                int spins = 0;
                while (*((volatile unsigned*)&g_hfdone) < target) {
                    if (++spins > 16) __nanosleep(64);
                }
                __threadfence();
            }
            __syncthreads();

            for (int i = tid; i < B_ * HID_; i += TPB) {
                int bb = i >> 6, hh = i & 63;
                float s = 0.f;
#pragma unroll
                for (int c = 0; c < 32; ++c) s += g_part[bb][c][hh];
                hg[i] = s;
            }
            __syncthreads();
            {   // 128 threads = 8 batches x 16 outputs
                int bb = tid >> 4, o = tid & 15;
                float acc = b2[o];
#pragma unroll
                for (int hh = 0; hh < HID_; ++hh)
                    acc += hg[bb * HID_ + hh] * W2[hh * OUT_ + o];
                out[bb * OUT_ + o] = acc;
            }
        }
    } else {
        // =================== HF BLOCKS (overlap with filter) ==============
        const int hbid = bid - GRIDF;
        const int chunk = hbid & 31;
        const int b = hbid >> 5;
        const int tx = tid & 63;
        const int ty = tid >> 6;
        const int gin = chunk >> 2;               // group owning my v-range

        if (tid == 0) sbase = *((volatile unsigned*)&g_cnt[gin * 32]);
        __syncthreads();
        const unsigned cbase = sbase;

        // ---- hf GEMM: acc = relu-pending (X@W1 + b1), overlapped --------
        for (int i = tid; i < F0_ * HID_; i += TPB) w1s[i] = W1[i];
        if (tid < HID_) b1s[tid] = b1[tid];
        __syncthreads();

        const int n = chunk * 64 + tx;
        const float* xr = X + ((size_t)b * N_ + n) * F0_;
        const int h0 = ty * 32;

        float acc[32];
#pragma unroll
        for (int h = 0; h < 32; ++h) acc[h] = b1s[h0 + h];

        for (int f0 = 0; f0 < F0_; f0 += 16) {
            float4 xv[4];
#pragma unroll
            for (int i = 0; i < 4; ++i)
                xv[i] = reinterpret_cast<const float4*>(xr + f0)[i];
            const float* xf = reinterpret_cast<const float*>(xv);
#pragma unroll
            for (int i = 0; i < 16; ++i) {
                float x = xf[i];
                const float4* wrow =
                    reinterpret_cast<const float4*>(&w1s[(f0 + i) * HID_ + h0]);
#pragma unroll
                for (int q = 0; q < 8; ++q) {
                    float4 wv = wrow[q];
                    acc[q * 4 + 0] += x * wv.x;
                    acc[q * 4 + 1] += x * wv.y;
                    acc[q * 4 + 2] += x * wv.z;
                    acc[q * 4 + 3] += x * wv.w;
                }
            }
        }

        // ---- wait: my group finished pass K (all 10 rounds) -------------
        if (tid == 0)
            wait_cnt((volatile unsigned*)&g_cnt[gin * 32],
                     cbase + 32u * (unsigned)K_);
        __syncthreads();

        // ---- reconstruct v for my 64-row chunk --------------------------
        // v[n] = r_K[n] = sum_c pr_K[c][n] + a_0 * (z_{K-1}[n] - sum_c pz_K[c][n])
        if (ty == 0) {
            int nn = chunk * 64 + tx;
            float s = 0.f, sp = 0.f;
#pragma unroll
            for (int c = 0; c < VCHUNKS; ++c) {
                s  += g_pz[K_][c][nn];
                sp += g_pr[K_][c][nn];
            }
            float znew = g_zv[K_ - 1][nn] - s;
            vsh[tx] = sp + theta[0] * znew;       // a_0 = theta_0
        }
        __syncthreads();

        float s = vsh[tx] * (1.0f / (float)N_);
#pragma unroll
        for (int h = 0; h < 32; ++h) acc[h] = fmaxf(acc[h], 0.f) * s;

#pragma unroll
        for (int h = 0; h < 32; ++h) {
            float v_ = acc[h];
            v_ += __shfl_xor_sync(0xffffffffu, v_, 16);
            v_ += __shfl_xor_sync(0xffffffffu, v_, 8);
            v_ += __shfl_xor_sync(0xffffffffu, v_, 4);
            v_ += __shfl_xor_sync(0xffffffffu, v_, 2);
            v_ += __shfl_xor_sync(0xffffffffu, v_, 1);
            acc[h] = v_;
        }
        int lane = tid & 31, warp = tid >> 5;
        if (lane == 0) {
#pragma unroll
            for (int h = 0; h < 32; ++h) red[warp][h] = acc[h];
        }
        __syncthreads();
        if (tid < 64) {
            int hh = tid & 31;
            int grp = tid >> 5;
            g_part[b][chunk][grp * 32 + hh] = red[grp * 2][hh] + red[grp * 2 + 1][hh];
        }

        // ---- signal completion ------------------------------------------
        __syncthreads();
        if (tid == 0) {
            __threadfence();
            atomicAdd(&g_hfdone, 1u);
        }
    }
}

// ---------------- launcher ----------------------------------------------
extern "C" void kernel_launch(void* const* d_in, const int* in_sizes, int n_in,
                              void* d_out, int out_size) {
    const float* X     = (const float*)d_in[0];
    const float* L     = (const float*)d_in[1];
    const float* W1    = (const float*)d_in[2];
    const float* b1    = (const float*)d_in[3];
    const float* W2    = (const float*)d_in[4];
    const float* b2    = (const float*)d_in[5];
    const float* theta = (const float*)d_in[6];
    float* out = (float*)d_out;

    mega_kernel<<<GRIDF + GRIDH, TPB, 32 * 1024>>>(X, L, W1, b1, W2, b2, theta, out);
}

// round 14
// speedup vs baseline: 2.2401x; 1.0444x over previous
#include <cuda_runtime.h>
#include <cuda_fp16.h>
#include <cstdint>

// Problem constants
#define B_   8
#define N_   2048
#define F0_  128
#define HID_ 64
#define OUT_ 16
#define K_   10

#define FBLK 128                 // filter blocks: 16 w-columns each, full 2048 rows
#define HBLK 128                 // hf blocks: 2 (b,chunk) assignments each
#define TPB  256
#define SLOTSTRIDE 520           // half2 words per slot group (64*8 + 8 pad)
#define DYNSMEM (32 * SLOTSTRIDE * 4)   // 66560 B

// ---------------- device scratch (static; no allocation) ----------------
__device__ float g_zv[K_ + 1][N_];           // z_j vectors (per-pass, no reuse)
__device__ float g_rv[K_ + 1][N_];           // r_j vectors (per-pass, no reuse)
__device__ float g_part[B_][32][HID_];       // per-(b,chunk) weighted partials
__device__ unsigned g_cnt[8 * 32];           // 8 group counters, 128B apart
__device__ unsigned g_hfdone = 0;            // monotonic hf completion counter

__constant__ float c_binom[K_ + 1] = {1.f, 10.f, 45.f, 120.f, 210.f, 252.f,
                                      210.f, 120.f, 45.f, 10.f, 1.f};

__device__ __forceinline__ void wait_cnt(volatile unsigned* ctr, unsigned target) {
    int spins = 0;
    while (*ctr < target) {
        if (++spins > 64) __nanosleep(32);
    }
    __threadfence();
}

__global__ __launch_bounds__(TPB) void mega_kernel(
    const float* __restrict__ X,  const float* __restrict__ L,
    const float* __restrict__ W1, const float* __restrict__ b1,
    const float* __restrict__ W2, const float* __restrict__ b2,
    const float* __restrict__ theta, float* __restrict__ out)
{
    extern __shared__ char dynsmem[];            // 65 KB: L-stripe or W1
    __half2* tile = reinterpret_cast<__half2*>(dynsmem);   // filter stripe
    float*   w1s  = reinterpret_cast<float*>(dynsmem);     // hf: W1

    __shared__ float szv[N_];            // full z_{j-1} (8 KB)
    __shared__ float srv[N_];            // full r_{j-1} (8 KB)
    __shared__ float4 redd[32][8];       // slot partials (az0,az1,ar0,ar1)
    __shared__ float b1s[HID_];
    __shared__ float redh[8][16];
    __shared__ float hg[B_ * HID_];
    __shared__ unsigned sbase[8];
    __shared__ unsigned shb;

    const int tid = threadIdx.x;
    const int bid = blockIdx.x;

    if (bid < FBLK) {
        // =================== FILTER BLOCKS (column stripes) ===============
        // snapshot counter bases at entry (monotonic; first arrival needs
        // the ~3us convert phase, snapshots land within ~100ns)
        if (tid < 8) sbase[tid] = *((volatile unsigned*)&g_cnt[tid * 32]);
        if (bid == 0 && tid == 0) shb = *((volatile unsigned*)&g_hfdone);

        // ---- Phase 0: convert my 2048x16-float column stripe to fp16 ----
        const int w0 = bid * 16;
        {
            const int q  = tid & 3;          // float4 within row
            const int r0 = tid >> 2;         // row base
#pragma unroll 4
            for (int g = 0; g < 32; ++g) {
                int v = g * 64 + r0;
                float4 f = *reinterpret_cast<const float4*>(
                    L + (size_t)v * N_ + w0 + q * 4);
                int off = (v & 31) * SLOTSTRIDE + (v >> 5) * 8 + q * 2;
                tile[off]     = __floats2half2_rn(f.x, f.y);
                tile[off + 1] = __floats2half2_rn(f.z, f.w);
            }
        }
        __syncthreads();

        const int c = tid & 7;               // half2 column (w = w0+2c, +1)
        const int s = tid >> 3;              // slot 0..31 (v ≡ s mod 32)
        const float thK = theta[K_];

        for (int j = 1; j <= K_; ++j) {
            if (j == 1) {
                for (int i = tid; i < N_; i += TPB) { szv[i] = 1.0f; srv[i] = thK; }
            } else {
                if (tid < 8)
                    wait_cnt((volatile unsigned*)&g_cnt[tid * 32],
                             sbase[tid] + 16u * (unsigned)(j - 1));
                __syncthreads();
                for (int i = tid; i < N_ / 4; i += TPB) {
                    reinterpret_cast<float4*>(szv)[i] =
                        reinterpret_cast<const float4*>(g_zv[j - 1])[i];
                    reinterpret_cast<float4*>(srv)[i] =
                        reinterpret_cast<const float4*>(g_rv[j - 1])[i];
                }
            }
            __syncthreads();

            // full-column dot: v = it*32 + s (conflict-free by layout)
            float az0 = 0.f, az1 = 0.f, ar0 = 0.f, ar1 = 0.f;
#pragma unroll
            for (int it = 0; it < 64; ++it) {
                int v = it * 32 + s;
                float2 f = __half22float2(tile[s * SLOTSTRIDE + it * 8 + c]);
                float zc = szv[v], rc = srv[v];
                az0 += f.x * zc;  az1 += f.y * zc;
                ar0 += f.x * rc;  ar1 += f.y * rc;
            }
            redd[s][c] = make_float4(az0, az1, ar0, ar1);
            __syncthreads();

            if (tid < 16) {                  // 16 outputs: in-block reduce
                int cc = tid >> 1, e = tid & 1;
                float zs = 0.f, rs = 0.f;
#pragma unroll
                for (int g = 0; g < 32; ++g) {
                    float4 p = redd[g][cc];
                    zs += e ? p.y : p.x;
                    rs += e ? p.w : p.z;
                }
                int w = w0 + 2 * cc + e;
                float znew = szv[w] - zs;
                float aj = theta[K_ - j] * c_binom[K_ - j];
                g_zv[j][w] = znew;
                g_rv[j][w] = rs + aj * znew;
            }
            __syncthreads();
            if (tid == 0) {                  // arrive on my group counter
                __threadfence();
                atomicAdd(&g_cnt[(bid & 7) * 32], 1u);
            }
        }

        // ---- block 0: wait for hf partials, emit logits -----------------
        if (bid == 0) {
            if (tid == 0) {
                unsigned target = shb + (unsigned)HBLK;
                int spins = 0;
                while (*((volatile unsigned*)&g_hfdone) < target) {
                    if (++spins > 16) __nanosleep(64);
                }
                __threadfence();
            }
            __syncthreads();

            for (int i = tid; i < B_ * HID_; i += TPB) {
                int bb = i >> 6, hh = i & 63;
                float sacc = 0.f;
#pragma unroll
                for (int ck = 0; ck < 32; ++ck) sacc += g_part[bb][ck][hh];
                hg[i] = sacc;
            }
            __syncthreads();
            if (tid < B_ * OUT_) {           // 128 threads = 8 x 16
                int bb = tid >> 4, o = tid & 15;
                float acc = b2[o];
#pragma unroll
                for (int hh = 0; hh < HID_; ++hh)
                    acc += hg[bb * HID_ + hh] * W2[hh * OUT_ + o];
                out[bb * OUT_ + o] = acc;
            }
        }
    } else {
        // =================== HF BLOCKS (overlap with filter) ==============
        const int hb = bid - FBLK;           // 0..127
        const int b = hb >> 4;               // batch
        const int c0 = (2 * hb) & 31;        // first of my two chunks

        if (tid < 8) sbase[tid] = *((volatile unsigned*)&g_cnt[tid * 32]);

        for (int i = tid; i < F0_ * HID_; i += TPB) w1s[i] = W1[i];
        if (tid < HID_) b1s[tid] = b1[tid];
        __syncthreads();

        const int tx = tid & 63;             // row within chunk
        const int ty = tid >> 6;             // 0..3 -> 16 hid each
        const int h0 = ty * 16;

        float acc[2][16];
#pragma unroll
        for (int a = 0; a < 2; ++a)
#pragma unroll
            for (int h = 0; h < 16; ++h) acc[a][h] = b1s[h0 + h];

#pragma unroll
        for (int a = 0; a < 2; ++a) {
            const int n = (c0 + a) * 64 + tx;
            const float* xr = X + ((size_t)b * N_ + n) * F0_;
            for (int f0 = 0; f0 < F0_; f0 += 16) {
                float4 xv[4];
#pragma unroll
                for (int i = 0; i < 4; ++i)
                    xv[i] = reinterpret_cast<const float4*>(xr + f0)[i];
                const float* xf = reinterpret_cast<const float*>(xv);
#pragma unroll
                for (int i = 0; i < 16; ++i) {
                    float x = xf[i];
                    const float4* wrow =
                        reinterpret_cast<const float4*>(&w1s[(f0 + i) * HID_ + h0]);
#pragma unroll
                    for (int q = 0; q < 4; ++q) {
                        float4 wv = wrow[q];
                        acc[a][q * 4 + 0] += x * wv.x;
                        acc[a][q * 4 + 1] += x * wv.y;
                        acc[a][q * 4 + 2] += x * wv.z;
                        acc[a][q * 4 + 3] += x * wv.w;
                    }
                }
            }
        }

        // ---- wait: filter chain done (all groups through pass K) --------
        if (tid < 8)
            wait_cnt((volatile unsigned*)&g_cnt[tid * 32],
                     sbase[tid] + 16u * (unsigned)K_);
        __syncthreads();

        const float invN = 1.0f / (float)N_;
        const int lane = tid & 31, warp = tid >> 5;
#pragma unroll
        for (int a = 0; a < 2; ++a) {
            const int chunk = c0 + a;
            float vn = g_rv[K_][chunk * 64 + tx] * invN;   // v[n]/N directly
#pragma unroll
            for (int h = 0; h < 16; ++h) {
                float val = fmaxf(acc[a][h], 0.f) * vn;
                val += __shfl_xor_sync(0xffffffffu, val, 16);
                val += __shfl_xor_sync(0xffffffffu, val, 8);
                val += __shfl_xor_sync(0xffffffffu, val, 4);
                val += __shfl_xor_sync(0xffffffffu, val, 2);
                val += __shfl_xor_sync(0xffffffffu, val, 1);
                acc[a][h] = val;
            }
            if (lane == 0) {
#pragma unroll
                for (int h = 0; h < 16; ++h) redh[warp][h] = acc[a][h];
            }
            __syncthreads();
            if (tid < 64) {
                int g = tid >> 4, hh = tid & 15;
                g_part[b][chunk][g * 16 + hh] =
                    redh[2 * g][hh] + redh[2 * g + 1][hh];
            }
            __syncthreads();
        }

        if (tid == 0) {
            __threadfence();
            atomicAdd(&g_hfdone, 1u);
        }
    }
}

// ---------------- launcher ----------------------------------------------
extern "C" void kernel_launch(void* const* d_in, const int* in_sizes, int n_in,
                              void* d_out, int out_size) {
    const float* X     = (const float*)d_in[0];
    const float* L     = (const float*)d_in[1];
    const float* W1    = (const float*)d_in[2];
    const float* b1    = (const float*)d_in[3];
    const float* W2    = (const float*)d_in[4];
    const float* b2    = (const float*)d_in[5];
    const float* theta = (const float*)d_in[6];
    float* out = (float*)d_out;

    cudaFuncSetAttribute(mega_kernel,
                         cudaFuncAttributeMaxDynamicSharedMemorySize, DYNSMEM);
    mega_kernel<<<FBLK + HBLK, TPB, DYNSMEM>>>(X, L, W1, b1, W2, b2, theta, out);
}